// round 1
// baseline (speedup 1.0000x reference)
#include <cuda_runtime.h>
#include <math.h>

// Problem constants
#define B_    8
#define S_    2048
#define D_    512
#define M_    (B_*S_)          // 16384 rows
#define SCALE 0.04419417382415922f   // BETA / sqrt(D)

// ---------------------------------------------------------------------------
// Scratch (device globals — no allocation allowed)
// ---------------------------------------------------------------------------
__device__ float g_q[M_*D_];
__device__ float g_k[M_*D_];
__device__ float g_v[M_*D_];
__device__ float g_att[M_*D_];
__device__ float g_onx[M_*D_];
__device__ float g_tmp[M_*D_];
__device__ float g_h[M_*D_];
__device__ float g_scores[(long long)B_*S_*S_];

// ---------------------------------------------------------------------------
// Tiled SGEMM: C = alpha * A @ B (+ bias), optional B transpose (NT), batched
// A: [M,K] row-major.  TRANSB=false: B [K,N] row-major.  TRANSB=true: B [N,K].
// Tiles 128x128x16, 256 threads, 8x8 per-thread microtile.
// Requires M%128==0, N%128==0, K%16==0 (true for all calls here).
// ---------------------------------------------------------------------------
template<bool TRANSB>
__global__ void __launch_bounds__(256, 2)
sgemm_kernel(const float* __restrict__ A, const float* __restrict__ Bm,
             const float* __restrict__ bias, float* __restrict__ C,
             int M, int N, int K, float alpha,
             long long strideA, long long strideB, long long strideC)
{
    const int bz = blockIdx.z;
    A  += (long long)bz * strideA;
    Bm += (long long)bz * strideB;
    C  += (long long)bz * strideC;

    __shared__ float As[16][128];
    __shared__ float Bs[16][128];

    const int tid = threadIdx.x;
    const int ty  = tid >> 4;      // 0..15 (row group)
    const int tx  = tid & 15;      // 0..15 (col group)
    const int m0  = blockIdx.y * 128;
    const int n0  = blockIdx.x * 128;

    float acc[8][8];
#pragma unroll
    for (int i = 0; i < 8; ++i)
#pragma unroll
        for (int j = 0; j < 8; ++j) acc[i][j] = 0.f;

    for (int k0 = 0; k0 < K; k0 += 16) {
        // Load A tile 128x16 (transpose into As[k][m])
#pragma unroll
        for (int it = 0; it < 2; ++it) {
            int idx = tid + it * 256;          // 0..511
            int r   = idx >> 2;                // 0..127
            int c4  = (idx & 3) << 2;          // 0,4,8,12
            float4 a = *(const float4*)(A + (long long)(m0 + r) * K + k0 + c4);
            As[c4 + 0][r] = a.x;
            As[c4 + 1][r] = a.y;
            As[c4 + 2][r] = a.z;
            As[c4 + 3][r] = a.w;
        }
        if (TRANSB) {
            // B rows are the N dimension: load B[n0+r, k0..k0+15], transpose
#pragma unroll
            for (int it = 0; it < 2; ++it) {
                int idx = tid + it * 256;
                int r   = idx >> 2;
                int c4  = (idx & 3) << 2;
                float4 b = *(const float4*)(Bm + (long long)(n0 + r) * K + k0 + c4);
                Bs[c4 + 0][r] = b.x;
                Bs[c4 + 1][r] = b.y;
                Bs[c4 + 2][r] = b.z;
                Bs[c4 + 3][r] = b.w;
            }
        } else {
            // B [K,N] row-major: load 16x128 directly
#pragma unroll
            for (int it = 0; it < 2; ++it) {
                int idx = tid + it * 256;
                int r   = idx >> 5;            // 0..15
                int c4  = (idx & 31) << 2;     // 0..124
                *(float4*)&Bs[r][c4] =
                    *(const float4*)(Bm + (long long)(k0 + r) * N + n0 + c4);
            }
        }
        __syncthreads();

#pragma unroll
        for (int kk = 0; kk < 16; ++kk) {
            float a[8], b[8];
            *(float4*)(a)     = *(float4*)&As[kk][ty * 8];
            *(float4*)(a + 4) = *(float4*)&As[kk][ty * 8 + 4];
            *(float4*)(b)     = *(float4*)&Bs[kk][tx * 8];
            *(float4*)(b + 4) = *(float4*)&Bs[kk][tx * 8 + 4];
#pragma unroll
            for (int i = 0; i < 8; ++i)
#pragma unroll
                for (int j = 0; j < 8; ++j)
                    acc[i][j] = fmaf(a[i], b[j], acc[i][j]);
        }
        __syncthreads();
    }

    // Epilogue
#pragma unroll
    for (int i = 0; i < 8; ++i) {
        int m = m0 + ty * 8 + i;
#pragma unroll
        for (int j = 0; j < 8; j += 4) {
            int n = n0 + tx * 8 + j;
            float4 o;
            o.x = acc[i][j + 0] * alpha;
            o.y = acc[i][j + 1] * alpha;
            o.z = acc[i][j + 2] * alpha;
            o.w = acc[i][j + 3] * alpha;
            if (bias) {
                o.x += bias[n + 0];
                o.y += bias[n + 1];
                o.z += bias[n + 2];
                o.w += bias[n + 3];
            }
            *(float4*)(C + (long long)m * N + n) = o;
        }
    }
}

// ---------------------------------------------------------------------------
// Row softmax over S_=2048 elements, one block (256 thr) per row.
// Scores already scaled by SCALE in the GEMM epilogue.
// ---------------------------------------------------------------------------
__global__ void __launch_bounds__(256)
softmax_kernel(float* __restrict__ s)
{
    const long long base = (long long)blockIdx.x * S_;
    const int tid = threadIdx.x;
    __shared__ float red[8];

    float v[8];
    float mx = -3.4e38f;
#pragma unroll
    for (int i = 0; i < 8; ++i) {
        v[i] = s[base + tid + i * 256];
        mx = fmaxf(mx, v[i]);
    }
#pragma unroll
    for (int o = 16; o; o >>= 1) mx = fmaxf(mx, __shfl_xor_sync(0xffffffffu, mx, o));
    if ((tid & 31) == 0) red[tid >> 5] = mx;
    __syncthreads();
    mx = red[0];
#pragma unroll
    for (int i = 1; i < 8; ++i) mx = fmaxf(mx, red[i]);
    __syncthreads();

    float sum = 0.f;
#pragma unroll
    for (int i = 0; i < 8; ++i) {
        v[i] = __expf(v[i] - mx);
        sum += v[i];
    }
#pragma unroll
    for (int o = 16; o; o >>= 1) sum += __shfl_xor_sync(0xffffffffu, sum, o);
    if ((tid & 31) == 0) red[tid >> 5] = sum;
    __syncthreads();
    float tot = 0.f;
#pragma unroll
    for (int i = 0; i < 8; ++i) tot += red[i];

    const float inv = 1.0f / tot;
#pragma unroll
    for (int i = 0; i < 8; ++i)
        s[base + tid + i * 256] = v[i] * inv;
}

// ---------------------------------------------------------------------------
// out = LayerNorm(x + att), row length D_=512, one block (256 thr) per row.
// ---------------------------------------------------------------------------
__global__ void __launch_bounds__(256)
add_ln_kernel(const float* __restrict__ x, const float* __restrict__ a,
              const float* __restrict__ gam, const float* __restrict__ bet,
              float* __restrict__ out)
{
    const long long base = (long long)blockIdx.x * D_;
    const int tid = threadIdx.x;
    __shared__ float r1[8], r2[8];

    float u0 = x[base + tid]       + a[base + tid];
    float u1 = x[base + tid + 256] + a[base + tid + 256];

    float s  = u0 + u1;
    float sq = u0 * u0 + u1 * u1;
#pragma unroll
    for (int o = 16; o; o >>= 1) {
        s  += __shfl_xor_sync(0xffffffffu, s,  o);
        sq += __shfl_xor_sync(0xffffffffu, sq, o);
    }
    if ((tid & 31) == 0) { r1[tid >> 5] = s; r2[tid >> 5] = sq; }
    __syncthreads();
    float ts = 0.f, tq = 0.f;
#pragma unroll
    for (int i = 0; i < 8; ++i) { ts += r1[i]; tq += r2[i]; }

    const float mean = ts * (1.0f / 512.0f);
    const float var  = tq * (1.0f / 512.0f) - mean * mean;
    const float rstd = rsqrtf(var + 1e-5f);

    out[base + tid]       = (u0 - mean) * rstd * gam[tid]       + bet[tid];
    out[base + tid + 256] = (u1 - mean) * rstd * gam[tid + 256] + bet[tid + 256];
}

// ---------------------------------------------------------------------------
// out = LayerNorm(gelu_exact(res + t)); t already contains GEMM bias.
// ---------------------------------------------------------------------------
__global__ void __launch_bounds__(256)
res_gelu_ln_kernel(const float* __restrict__ t, const float* __restrict__ res,
                   const float* __restrict__ gam, const float* __restrict__ bet,
                   float* __restrict__ out)
{
    const long long base = (long long)blockIdx.x * D_;
    const int tid = threadIdx.x;
    __shared__ float r1[8], r2[8];

    float u0 = res[base + tid]       + t[base + tid];
    float u1 = res[base + tid + 256] + t[base + tid + 256];
    // exact GELU: 0.5*u*(1+erf(u/sqrt(2)))
    float g0 = 0.5f * u0 * (1.0f + erff(u0 * 0.70710678118654752f));
    float g1 = 0.5f * u1 * (1.0f + erff(u1 * 0.70710678118654752f));

    float s  = g0 + g1;
    float sq = g0 * g0 + g1 * g1;
#pragma unroll
    for (int o = 16; o; o >>= 1) {
        s  += __shfl_xor_sync(0xffffffffu, s,  o);
        sq += __shfl_xor_sync(0xffffffffu, sq, o);
    }
    if ((tid & 31) == 0) { r1[tid >> 5] = s; r2[tid >> 5] = sq; }
    __syncthreads();
    float ts = 0.f, tq = 0.f;
#pragma unroll
    for (int i = 0; i < 8; ++i) { ts += r1[i]; tq += r2[i]; }

    const float mean = ts * (1.0f / 512.0f);
    const float var  = tq * (1.0f / 512.0f) - mean * mean;
    const float rstd = rsqrtf(var + 1e-5f);

    out[base + tid]       = (g0 - mean) * rstd * gam[tid]       + bet[tid];
    out[base + tid + 256] = (g1 - mean) * rstd * gam[tid + 256] + bet[tid + 256];
}

// ---------------------------------------------------------------------------
// Launch sequence (graph-capturable: kernel launches only)
// ---------------------------------------------------------------------------
extern "C" void kernel_launch(void* const* d_in, const int* in_sizes, int n_in,
                              void* d_out, int out_size)
{
    const float* x    = (const float*)d_in[0];
    const float* Wq   = (const float*)d_in[1];
    const float* bq   = (const float*)d_in[2];
    const float* Wk   = (const float*)d_in[3];
    const float* bk   = (const float*)d_in[4];
    const float* Wv   = (const float*)d_in[5];
    const float* bv   = (const float*)d_in[6];
    const float* ln0g = (const float*)d_in[7];
    const float* ln0b = (const float*)d_in[8];
    const float* W1   = (const float*)d_in[9];
    const float* b1   = (const float*)d_in[10];
    const float* ln1g = (const float*)d_in[11];
    const float* ln1b = (const float*)d_in[12];
    const float* W2   = (const float*)d_in[13];
    const float* b2   = (const float*)d_in[14];
    const float* ln2g = (const float*)d_in[15];
    const float* ln2b = (const float*)d_in[16];
    const float* W3   = (const float*)d_in[17];
    const float* b3   = (const float*)d_in[18];

    float *q, *k, *v, *att, *onx, *tmp, *h, *sc;
    cudaGetSymbolAddress((void**)&q,   g_q);
    cudaGetSymbolAddress((void**)&k,   g_k);
    cudaGetSymbolAddress((void**)&v,   g_v);
    cudaGetSymbolAddress((void**)&att, g_att);
    cudaGetSymbolAddress((void**)&onx, g_onx);
    cudaGetSymbolAddress((void**)&tmp, g_tmp);
    cudaGetSymbolAddress((void**)&h,   g_h);
    cudaGetSymbolAddress((void**)&sc,  g_scores);

    const dim3 t(256);
    const long long sSD = (long long)S_ * D_;
    const long long sSS = (long long)S_ * S_;

    // QKV projections: [16384,512] @ [512,512] + bias
    sgemm_kernel<false><<<dim3(4, 128, 1), t>>>(x, Wq, bq, q, M_, D_, D_, 1.f, 0, 0, 0);
    sgemm_kernel<false><<<dim3(4, 128, 1), t>>>(x, Wk, bk, k, M_, D_, D_, 1.f, 0, 0, 0);
    sgemm_kernel<false><<<dim3(4, 128, 1), t>>>(x, Wv, bv, v, M_, D_, D_, 1.f, 0, 0, 0);

    // scores[b] = (q_b @ k_b^T) * SCALE   (batched NT GEMM)
    sgemm_kernel<true><<<dim3(16, 16, B_), t>>>(q, k, nullptr, sc,
                                                S_, S_, D_, SCALE, sSD, sSD, sSS);

    // softmax over last axis
    softmax_kernel<<<M_, t>>>(sc);

    // att[b] = w_b @ v_b   (batched NN GEMM, K=2048)
    sgemm_kernel<false><<<dim3(4, 16, B_), t>>>(sc, v, nullptr, att,
                                                S_, D_, S_, 1.f, sSS, sSD, sSD);

    // out_nxt = LN(x + att)
    add_ln_kernel<<<M_, t>>>(x, att, ln0g, ln0b, onx);

    // h1 = LN(gelu(out_nxt + out_nxt@W1 + b1))
    sgemm_kernel<false><<<dim3(4, 128, 1), t>>>(onx, W1, b1, tmp, M_, D_, D_, 1.f, 0, 0, 0);
    res_gelu_ln_kernel<<<M_, t>>>(tmp, onx, ln1g, ln1b, h);

    // h2 = LN(gelu(out_nxt + h1@W2 + b2))
    sgemm_kernel<false><<<dim3(4, 128, 1), t>>>(h, W2, b2, tmp, M_, D_, D_, 1.f, 0, 0, 0);
    res_gelu_ln_kernel<<<M_, t>>>(tmp, onx, ln2g, ln2b, h);

    // out = h2 @ W3 + b3
    sgemm_kernel<false><<<dim3(4, 128, 1), t>>>(h, W3, b3, (float*)d_out,
                                                M_, D_, D_, 1.f, 0, 0, 0);
}

// round 4
// speedup vs baseline: 2.0819x; 2.0819x over previous
#include <cuda_runtime.h>
#include <cuda_bf16.h>
#include <cstdint>
#include <math.h>

#define B_    8
#define S_    2048
#define D_    512
#define M_    (B_*S_)
#define SCALE 0.04419417382415922f

// ---------------------------------------------------------------------------
// PTX helpers (arch-agnostic: cp.async / ldmatrix / mma.sync only)
// ---------------------------------------------------------------------------
__device__ __forceinline__ uint32_t smem_to_u32(const void* p) {
    uint32_t a;
    asm("{ .reg .u64 t; cvta.to.shared.u64 t, %1; cvt.u32.u64 %0, t; }"
        : "=r"(a) : "l"(p));
    return a;
}
#define CP_ASYNC16(dst, src) \
    asm volatile("cp.async.cg.shared.global [%0], [%1], 16;" :: "r"(dst), "l"(src))
#define CP_COMMIT() asm volatile("cp.async.commit_group;")
#define CP_WAIT1()  asm volatile("cp.async.wait_group 1;")
#define CP_WAIT0()  asm volatile("cp.async.wait_group 0;")

__device__ __forceinline__ void ldsm4(uint32_t* r, uint32_t a) {
    asm volatile("ldmatrix.sync.aligned.m8n8.x4.shared.b16 {%0,%1,%2,%3}, [%4];"
        : "=r"(r[0]), "=r"(r[1]), "=r"(r[2]), "=r"(r[3]) : "r"(a));
}
__device__ __forceinline__ void ldsm2(uint32_t* r, uint32_t a) {
    asm volatile("ldmatrix.sync.aligned.m8n8.x2.shared.b16 {%0,%1}, [%2];"
        : "=r"(r[0]), "=r"(r[1]) : "r"(a));
}
__device__ __forceinline__ void mma16816(float* c, const uint32_t* a, const uint32_t* b) {
    asm volatile("mma.sync.aligned.m16n8k16.row.col.f32.bf16.bf16.f32 "
        "{%0,%1,%2,%3}, {%4,%5,%6,%7}, {%8,%9}, {%0,%1,%2,%3};"
        : "+f"(c[0]), "+f"(c[1]), "+f"(c[2]), "+f"(c[3])
        : "r"(a[0]), "r"(a[1]), "r"(a[2]), "r"(a[3]), "r"(b[0]), "r"(b[1]));
}

// ---------------------------------------------------------------------------
// Scratch (device globals)
// ---------------------------------------------------------------------------
#define AL __align__(256)
__device__ AL __nv_bfloat16 g_xh[M_*D_],  g_xl[M_*D_];
__device__ AL __nv_bfloat16 g_qh[M_*D_],  g_ql[M_*D_];
__device__ AL __nv_bfloat16 g_kh[M_*D_],  g_kl[M_*D_];
__device__ AL __nv_bfloat16 g_vth[M_*D_], g_vtl[M_*D_];
__device__ AL __nv_bfloat16 g_oh[M_*D_],  g_ol[M_*D_];
__device__ AL __nv_bfloat16 g_hh[M_*D_],  g_hl[M_*D_];
__device__ AL __nv_bfloat16 g_wh[(long long)B_*S_*S_], g_wl[(long long)B_*S_*S_];
__device__ AL __nv_bfloat16 g_wth[6*D_*D_], g_wtl[6*D_*D_];
__device__ AL float g_sc[(long long)B_*S_*S_];
__device__ AL float g_att[M_*D_];
__device__ AL float g_onx[M_*D_];
__device__ AL float g_tmp[M_*D_];

// ---------------------------------------------------------------------------
// Split-bf16 tensor-core GEMM: C = alpha * (A @ B^T) (+ bias)
// A (hi/lo) [M,K] row-major, B (hi/lo) [N,K] row-major.
// 128x128 block, 8 warps (2x4), warp tile 64x32, K-chunk 32, double-buffered
// cp.async. OUT_MODE 0: fp32; 1: split hi/lo bf16.
// BIAS_MODE 0: none; 1: per-col (n); 2: per-row (m).
// SMEM: 2 stages x 4 arrays x (128 rows x 80B) = 81920 bytes.
// ---------------------------------------------------------------------------
#define STAGE_BYTES 40960
#define ARR_BYTES   10240
#define GEMM_SMEM   (2*STAGE_BYTES)

__device__ __forceinline__ void load_chunk(uint32_t sbase,
    const __nv_bfloat16* s0, const __nv_bfloat16* s1,
    const __nv_bfloat16* s2, const __nv_bfloat16* s3,
    long long lda, long long ldb, int k0, int tid)
{
    const __nv_bfloat16* src[4] = { s0, s1, s2, s3 };
    const long long ldt[4] = { lda, lda, ldb, ldb };
#pragma unroll
    for (int t = 0; t < 4; ++t) {
#pragma unroll
        for (int j = 0; j < 2; ++j) {
            int idx = tid + j * 256;
            int r = idx >> 2, seg = idx & 3;
            const void* g = src[t] + (long long)r * ldt[t] + k0 + seg * 8;
            uint32_t d = sbase + t * ARR_BYTES + r * 80 + seg * 16;
            CP_ASYNC16(d, g);
        }
    }
    CP_COMMIT();
}

template<int OUT_MODE, int BIAS_MODE>
__global__ void __launch_bounds__(256, 1)
gemm_tc(const __nv_bfloat16* __restrict__ Ah, const __nv_bfloat16* __restrict__ Al,
        long long lda, long long sA,
        const __nv_bfloat16* __restrict__ Bh, const __nv_bfloat16* __restrict__ Bl,
        long long ldb, long long sB,
        float* __restrict__ Cf, __nv_bfloat16* __restrict__ Ch,
        __nv_bfloat16* __restrict__ Cl, long long ldc, long long sC,
        const float* __restrict__ bias, float alpha, int K)
{
    extern __shared__ __align__(16) char smem[];
    const uint32_t smem_base = smem_to_u32(smem);
    const int tid  = threadIdx.x;
    const int wid  = tid >> 5;
    const int lane = tid & 31;
    const int wm = wid >> 2;              // 0..1
    const int wn = wid & 3;               // 0..3
    const long long bz = blockIdx.z;
    const long long m0 = (long long)blockIdx.y * 128;
    const long long n0 = (long long)blockIdx.x * 128;

    const __nv_bfloat16* pAh = Ah + bz * sA + m0 * lda;
    const __nv_bfloat16* pAl = Al + bz * sA + m0 * lda;
    const __nv_bfloat16* pBh = Bh + bz * sB + n0 * ldb;
    const __nv_bfloat16* pBl = Bl + bz * sB + n0 * ldb;

    float acc[4][4][4];
#pragma unroll
    for (int i = 0; i < 4; ++i)
#pragma unroll
        for (int j = 0; j < 4; ++j)
#pragma unroll
            for (int r = 0; r < 4; ++r) acc[i][j][r] = 0.f;

    // ldmatrix per-lane address components
    const int q   = lane >> 3;            // 0..3
    const int rim = lane & 7;
    const int aRow = wm * 64 + (q & 1) * 8 + rim;       // + i*16
    const int aKc  = (q >> 1) * 8;                      // + kk*16
    const int bl_  = lane & 15;
    const int bRow = wn * 32 + (bl_ & 7);               // + j*8
    const int bKc  = (bl_ >> 3) * 8;                    // + kk*16

    const int nch = K >> 5;
    load_chunk(smem_base, pAh, pAl, pBh, pBl, lda, ldb, 0, tid);

    for (int c = 0; c < nch; ++c) {
        if (c + 1 < nch) {
            load_chunk(smem_base + ((c + 1) & 1) * STAGE_BYTES,
                       pAh, pAl, pBh, pBl, lda, ldb, (c + 1) << 5, tid);
            CP_WAIT1();
        } else {
            CP_WAIT0();
        }
        __syncthreads();

        const uint32_t sb = smem_base + (c & 1) * STAGE_BYTES;
        const uint32_t aH = sb, aL = sb + ARR_BYTES;
        const uint32_t bH = sb + 2 * ARR_BYTES, bL = sb + 3 * ARR_BYTES;
#pragma unroll
        for (int kk = 0; kk < 2; ++kk) {
            uint32_t ah[4][4], al[4][4];
#pragma unroll
            for (int i = 0; i < 4; ++i) {
                uint32_t off = (uint32_t)(aRow + i * 16) * 80 + (uint32_t)(kk * 16 + aKc) * 2;
                ldsm4(ah[i], aH + off);
                ldsm4(al[i], aL + off);
            }
#pragma unroll
            for (int j = 0; j < 4; ++j) {
                uint32_t offB = (uint32_t)(bRow + j * 8) * 80 + (uint32_t)(kk * 16 + bKc) * 2;
                uint32_t bh[2], blo[2];
                ldsm2(bh,  bH + offB);
                ldsm2(blo, bL + offB);
#pragma unroll
                for (int i = 0; i < 4; ++i) {
                    mma16816(acc[i][j], ah[i], bh);
                    mma16816(acc[i][j], ah[i], blo);
                    mma16816(acc[i][j], al[i], bh);
                }
            }
        }
        __syncthreads();
    }

    // Epilogue
    const int g = lane >> 2, t = lane & 3;
#pragma unroll
    for (int i = 0; i < 4; ++i) {
#pragma unroll
        for (int half = 0; half < 2; ++half) {
            const long long m = m0 + wm * 64 + i * 16 + g + half * 8;
            float brow = 0.f;
            if (BIAS_MODE == 2) brow = bias[m];
#pragma unroll
            for (int j = 0; j < 4; ++j) {
                const long long n = n0 + wn * 32 + j * 8 + t * 2;
                float v0 = acc[i][j][half * 2 + 0] * alpha;
                float v1 = acc[i][j][half * 2 + 1] * alpha;
                if (BIAS_MODE == 1) { v0 += bias[n]; v1 += bias[n + 1]; }
                if (BIAS_MODE == 2) { v0 += brow;    v1 += brow; }
                const long long cb = bz * sC + m * ldc + n;
                if (OUT_MODE == 0) {
                    *(float2*)(Cf + cb) = make_float2(v0, v1);
                } else {
                    __nv_bfloat16 h0 = __float2bfloat16(v0);
                    __nv_bfloat16 h1 = __float2bfloat16(v1);
                    __nv_bfloat162 h2, l2;
                    h2.x = h0; h2.y = h1;
                    l2.x = __float2bfloat16(v0 - __bfloat162float(h0));
                    l2.y = __float2bfloat16(v1 - __bfloat162float(h1));
                    *(__nv_bfloat162*)(Ch + cb) = h2;
                    *(__nv_bfloat162*)(Cl + cb) = l2;
                }
            }
        }
    }
}

// ---------------------------------------------------------------------------
// fp32 -> (hi, lo) bf16 split, elementwise
// ---------------------------------------------------------------------------
__global__ void __launch_bounds__(256)
split_kernel(const float* __restrict__ in, __nv_bfloat16* __restrict__ oh,
             __nv_bfloat16* __restrict__ ol, int n)
{
    int i = blockIdx.x * 256 + threadIdx.x;
    for (; i < n; i += gridDim.x * 256) {
        float v = in[i];
        __nv_bfloat16 h = __float2bfloat16(v);
        oh[i] = h;
        ol[i] = __float2bfloat16(v - __bfloat162float(h));
    }
}

// transpose + split: T[c, r] = W[r, c];  W is [R, C]
__global__ void __launch_bounds__(256)
tsplit_kernel(const float* __restrict__ W, __nv_bfloat16* __restrict__ Th,
              __nv_bfloat16* __restrict__ Tl, int R, int C)
{
    __shared__ float tile[32][33];
    const int c0 = blockIdx.x * 32, r0 = blockIdx.y * 32;
    const int tx = threadIdx.x & 31, ty = threadIdx.x >> 5;
#pragma unroll
    for (int i = 0; i < 32; i += 8)
        tile[ty + i][tx] = W[(long long)(r0 + ty + i) * C + c0 + tx];
    __syncthreads();
#pragma unroll
    for (int i = 0; i < 32; i += 8) {
        float v = tile[tx][ty + i];
        __nv_bfloat16 h = __float2bfloat16(v);
        long long o = (long long)(c0 + ty + i) * R + r0 + tx;
        Th[o] = h;
        Tl[o] = __float2bfloat16(v - __bfloat162float(h));
    }
}

// ---------------------------------------------------------------------------
// Row softmax (S_=2048) -> split bf16 output
// ---------------------------------------------------------------------------
__global__ void __launch_bounds__(256)
softmax_split_kernel(const float* __restrict__ s, __nv_bfloat16* __restrict__ wh,
                     __nv_bfloat16* __restrict__ wl)
{
    const long long base = (long long)blockIdx.x * S_ + threadIdx.x * 8;
    const int tid = threadIdx.x;
    __shared__ float red[8];

    float v[8];
    *(float4*)(v)     = *(const float4*)(s + base);
    *(float4*)(v + 4) = *(const float4*)(s + base + 4);

    float mx = v[0];
#pragma unroll
    for (int i = 1; i < 8; ++i) mx = fmaxf(mx, v[i]);
#pragma unroll
    for (int o = 16; o; o >>= 1) mx = fmaxf(mx, __shfl_xor_sync(0xffffffffu, mx, o));
    if ((tid & 31) == 0) red[tid >> 5] = mx;
    __syncthreads();
    mx = red[0];
#pragma unroll
    for (int i = 1; i < 8; ++i) mx = fmaxf(mx, red[i]);
    __syncthreads();

    float sum = 0.f;
#pragma unroll
    for (int i = 0; i < 8; ++i) { v[i] = __expf(v[i] - mx); sum += v[i]; }
#pragma unroll
    for (int o = 16; o; o >>= 1) sum += __shfl_xor_sync(0xffffffffu, sum, o);
    if ((tid & 31) == 0) red[tid >> 5] = sum;
    __syncthreads();
    float tot = 0.f;
#pragma unroll
    for (int i = 0; i < 8; ++i) tot += red[i];

    const float inv = 1.0f / tot;
#pragma unroll
    for (int i = 0; i < 8; i += 2) {
        float a = v[i] * inv, b = v[i+1] * inv;
        __nv_bfloat16 h0 = __float2bfloat16(a);
        __nv_bfloat16 h1 = __float2bfloat16(b);
        __nv_bfloat162 h2, l2;
        h2.x = h0; h2.y = h1;
        l2.x = __float2bfloat16(a - __bfloat162float(h0));
        l2.y = __float2bfloat16(b - __bfloat162float(h1));
        *(__nv_bfloat162*)(wh + base + i) = h2;
        *(__nv_bfloat162*)(wl + base + i) = l2;
    }
}

// ---------------------------------------------------------------------------
// out = LN(x + att) -> fp32 onx + split bf16
// ---------------------------------------------------------------------------
__global__ void __launch_bounds__(256)
add_ln_kernel(const float* __restrict__ x, const float* __restrict__ a,
              const float* __restrict__ gam, const float* __restrict__ bet,
              float* __restrict__ out, __nv_bfloat16* __restrict__ oh,
              __nv_bfloat16* __restrict__ ol)
{
    const long long base = (long long)blockIdx.x * D_;
    const int tid = threadIdx.x;
    __shared__ float r1[8], r2[8];
    const int i0 = tid * 2;

    float2 xa = *(const float2*)(x + base + i0);
    float2 aa = *(const float2*)(a + base + i0);
    float u0 = xa.x + aa.x, u1 = xa.y + aa.y;

    float s = u0 + u1, sq = u0*u0 + u1*u1;
#pragma unroll
    for (int o = 16; o; o >>= 1) {
        s  += __shfl_xor_sync(0xffffffffu, s,  o);
        sq += __shfl_xor_sync(0xffffffffu, sq, o);
    }
    if ((tid & 31) == 0) { r1[tid >> 5] = s; r2[tid >> 5] = sq; }
    __syncthreads();
    float ts = 0.f, tq = 0.f;
#pragma unroll
    for (int i = 0; i < 8; ++i) { ts += r1[i]; tq += r2[i]; }
    const float mean = ts * (1.0f/512.0f);
    const float var  = tq * (1.0f/512.0f) - mean*mean;
    const float rstd = rsqrtf(var + 1e-5f);

    float o0 = (u0 - mean)*rstd*gam[i0]   + bet[i0];
    float o1 = (u1 - mean)*rstd*gam[i0+1] + bet[i0+1];
    *(float2*)(out + base + i0) = make_float2(o0, o1);
    __nv_bfloat16 h0 = __float2bfloat16(o0), h1 = __float2bfloat16(o1);
    __nv_bfloat162 h2, l2;
    h2.x = h0; h2.y = h1;
    l2.x = __float2bfloat16(o0 - __bfloat162float(h0));
    l2.y = __float2bfloat16(o1 - __bfloat162float(h1));
    *(__nv_bfloat162*)(oh + base + i0) = h2;
    *(__nv_bfloat162*)(ol + base + i0) = l2;
}

// out = LN(gelu(res + t)) -> split bf16 only
__global__ void __launch_bounds__(256)
res_gelu_ln_kernel(const float* __restrict__ t, const float* __restrict__ res,
                   const float* __restrict__ gam, const float* __restrict__ bet,
                   __nv_bfloat16* __restrict__ oh, __nv_bfloat16* __restrict__ ol)
{
    const long long base = (long long)blockIdx.x * D_;
    const int tid = threadIdx.x;
    __shared__ float r1[8], r2[8];
    const int i0 = tid * 2;

    float2 ta = *(const float2*)(t + base + i0);
    float2 ra = *(const float2*)(res + base + i0);
    float u0 = ra.x + ta.x, u1 = ra.y + ta.y;
    float g0 = 0.5f * u0 * (1.0f + erff(u0 * 0.70710678118654752f));
    float g1 = 0.5f * u1 * (1.0f + erff(u1 * 0.70710678118654752f));

    float s = g0 + g1, sq = g0*g0 + g1*g1;
#pragma unroll
    for (int o = 16; o; o >>= 1) {
        s  += __shfl_xor_sync(0xffffffffu, s,  o);
        sq += __shfl_xor_sync(0xffffffffu, sq, o);
    }
    if ((tid & 31) == 0) { r1[tid >> 5] = s; r2[tid >> 5] = sq; }
    __syncthreads();
    float ts = 0.f, tq = 0.f;
#pragma unroll
    for (int i = 0; i < 8; ++i) { ts += r1[i]; tq += r2[i]; }
    const float mean = ts * (1.0f/512.0f);
    const float var  = tq * (1.0f/512.0f) - mean*mean;
    const float rstd = rsqrtf(var + 1e-5f);

    float o0 = (g0 - mean)*rstd*gam[i0]   + bet[i0];
    float o1 = (g1 - mean)*rstd*gam[i0+1] + bet[i0+1];
    __nv_bfloat16 h0 = __float2bfloat16(o0), h1 = __float2bfloat16(o1);
    __nv_bfloat162 h2, l2;
    h2.x = h0; h2.y = h1;
    l2.x = __float2bfloat16(o0 - __bfloat162float(h0));
    l2.y = __float2bfloat16(o1 - __bfloat162float(h1));
    *(__nv_bfloat162*)(oh + base + i0) = h2;
    *(__nv_bfloat162*)(ol + base + i0) = l2;
}

// ---------------------------------------------------------------------------
// Launch sequence
// ---------------------------------------------------------------------------
extern "C" void kernel_launch(void* const* d_in, const int* in_sizes, int n_in,
                              void* d_out, int out_size)
{
    const float* x    = (const float*)d_in[0];
    const float* Wq   = (const float*)d_in[1];
    const float* bq   = (const float*)d_in[2];
    const float* Wk   = (const float*)d_in[3];
    const float* bk   = (const float*)d_in[4];
    const float* Wv   = (const float*)d_in[5];
    const float* bv   = (const float*)d_in[6];
    const float* ln0g = (const float*)d_in[7];
    const float* ln0b = (const float*)d_in[8];
    const float* W1   = (const float*)d_in[9];
    const float* b1   = (const float*)d_in[10];
    const float* ln1g = (const float*)d_in[11];
    const float* ln1b = (const float*)d_in[12];
    const float* W2   = (const float*)d_in[13];
    const float* b2   = (const float*)d_in[14];
    const float* ln2g = (const float*)d_in[15];
    const float* ln2b = (const float*)d_in[16];
    const float* W3   = (const float*)d_in[17];
    const float* b3   = (const float*)d_in[18];

    __nv_bfloat16 *xh, *xl, *qh, *ql, *kh, *kl, *vth, *vtl, *oh, *ol, *hh, *hl,
                  *wh, *wl, *wth, *wtl;
    float *sc, *att, *onx, *tmp;
    cudaGetSymbolAddress((void**)&xh,  g_xh);  cudaGetSymbolAddress((void**)&xl,  g_xl);
    cudaGetSymbolAddress((void**)&qh,  g_qh);  cudaGetSymbolAddress((void**)&ql,  g_ql);
    cudaGetSymbolAddress((void**)&kh,  g_kh);  cudaGetSymbolAddress((void**)&kl,  g_kl);
    cudaGetSymbolAddress((void**)&vth, g_vth); cudaGetSymbolAddress((void**)&vtl, g_vtl);
    cudaGetSymbolAddress((void**)&oh,  g_oh);  cudaGetSymbolAddress((void**)&ol,  g_ol);
    cudaGetSymbolAddress((void**)&hh,  g_hh);  cudaGetSymbolAddress((void**)&hl,  g_hl);
    cudaGetSymbolAddress((void**)&wh,  g_wh);  cudaGetSymbolAddress((void**)&wl,  g_wl);
    cudaGetSymbolAddress((void**)&wth, g_wth); cudaGetSymbolAddress((void**)&wtl, g_wtl);
    cudaGetSymbolAddress((void**)&sc,  g_sc);  cudaGetSymbolAddress((void**)&att, g_att);
    cudaGetSymbolAddress((void**)&onx, g_onx); cudaGetSymbolAddress((void**)&tmp, g_tmp);

    cudaFuncSetAttribute(gemm_tc<0,0>, cudaFuncAttributeMaxDynamicSharedMemorySize, GEMM_SMEM);
    cudaFuncSetAttribute(gemm_tc<0,1>, cudaFuncAttributeMaxDynamicSharedMemorySize, GEMM_SMEM);
    cudaFuncSetAttribute(gemm_tc<1,1>, cudaFuncAttributeMaxDynamicSharedMemorySize, GEMM_SMEM);
    cudaFuncSetAttribute(gemm_tc<1,2>, cudaFuncAttributeMaxDynamicSharedMemorySize, GEMM_SMEM);

    const dim3 t256(256);
    const long long DD = (long long)D_ * D_;
    const long long sSD = (long long)S_ * D_;
    const long long sSS = (long long)S_ * S_;

    tsplit_kernel<<<dim3(16,16), t256>>>(Wq, wth + 0*DD, wtl + 0*DD, D_, D_);
    tsplit_kernel<<<dim3(16,16), t256>>>(Wk, wth + 1*DD, wtl + 1*DD, D_, D_);
    tsplit_kernel<<<dim3(16,16), t256>>>(Wv, wth + 2*DD, wtl + 2*DD, D_, D_);
    tsplit_kernel<<<dim3(16,16), t256>>>(W1, wth + 3*DD, wtl + 3*DD, D_, D_);
    tsplit_kernel<<<dim3(16,16), t256>>>(W2, wth + 4*DD, wtl + 4*DD, D_, D_);
    tsplit_kernel<<<dim3(16,16), t256>>>(W3, wth + 5*DD, wtl + 5*DD, D_, D_);

    split_kernel<<<4096, t256>>>(x, xh, xl, M_*D_);

    // q = x @ Wq + bq ; k = x @ Wk + bk  (split out)
    gemm_tc<1,1><<<dim3(4,128,1), t256, GEMM_SMEM>>>(xh, xl, D_, 0,
        wth + 0*DD, wtl + 0*DD, D_, 0, nullptr, qh, ql, D_, 0, bq, 1.f, D_);
    gemm_tc<1,1><<<dim3(4,128,1), t256, GEMM_SMEM>>>(xh, xl, D_, 0,
        wth + 1*DD, wtl + 1*DD, D_, 0, nullptr, kh, kl, D_, 0, bk, 1.f, D_);

    // vT[feat, token] = Wv^T @ x^T + bv (row bias), ldc = 16384
    gemm_tc<1,2><<<dim3(128,4,1), t256, GEMM_SMEM>>>(wth + 2*DD, wtl + 2*DD, D_, 0,
        xh, xl, D_, 0, nullptr, vth, vtl, (long long)M_, 0, bv, 1.f, D_);

    // scores[b] = SCALE * q_b @ k_b^T  (fp32 out)
    gemm_tc<0,0><<<dim3(16,16,B_), t256, GEMM_SMEM>>>(qh, ql, D_, sSD,
        kh, kl, D_, sSD, sc, nullptr, nullptr, S_, sSS, nullptr, SCALE, D_);

    softmax_split_kernel<<<M_, t256>>>(sc, wh, wl);

    // att[b] = w_b @ v_b  (B = vT, ldb = 16384, batch col offset 2048)
    gemm_tc<0,0><<<dim3(4,16,B_), t256, GEMM_SMEM>>>(wh, wl, S_, sSS,
        vth, vtl, (long long)M_, (long long)S_, att, nullptr, nullptr, D_, sSD,
        nullptr, 1.f, S_);

    add_ln_kernel<<<M_, t256>>>(x, att, ln0g, ln0b, onx, oh, ol);

    gemm_tc<0,1><<<dim3(4,128,1), t256, GEMM_SMEM>>>(oh, ol, D_, 0,
        wth + 3*DD, wtl + 3*DD, D_, 0, tmp, nullptr, nullptr, D_, 0, b1, 1.f, D_);
    res_gelu_ln_kernel<<<M_, t256>>>(tmp, onx, ln1g, ln1b, hh, hl);

    gemm_tc<0,1><<<dim3(4,128,1), t256, GEMM_SMEM>>>(hh, hl, D_, 0,
        wth + 4*DD, wtl + 4*DD, D_, 0, tmp, nullptr, nullptr, D_, 0, b2, 1.f, D_);
    res_gelu_ln_kernel<<<M_, t256>>>(tmp, onx, ln2g, ln2b, hh, hl);

    gemm_tc<0,1><<<dim3(4,128,1), t256, GEMM_SMEM>>>(hh, hl, D_, 0,
        wth + 5*DD, wtl + 5*DD, D_, 0, (float*)d_out, nullptr, nullptr, D_, 0,
        b3, 1.f, D_);
}

// round 5
// speedup vs baseline: 3.8831x; 1.8652x over previous
#include <cuda_runtime.h>
#include <cuda_bf16.h>
#include <cstdint>
#include <math.h>

#define B_    8
#define S_    2048
#define D_    512
#define M_    (B_*S_)
#define SCALE 0.04419417382415922f

// ---------------------------------------------------------------------------
// PTX helpers (arch-agnostic)
// ---------------------------------------------------------------------------
__device__ __forceinline__ uint32_t smem_to_u32(const void* p) {
    uint32_t a;
    asm("{ .reg .u64 t; cvta.to.shared.u64 t, %1; cvt.u32.u64 %0, t; }"
        : "=r"(a) : "l"(p));
    return a;
}
#define CP_ASYNC16(dst, src) \
    asm volatile("cp.async.cg.shared.global [%0], [%1], 16;" :: "r"(dst), "l"(src))
#define CP_COMMIT() asm volatile("cp.async.commit_group;")
#define CP_WAIT1()  asm volatile("cp.async.wait_group 1;")
#define CP_WAIT0()  asm volatile("cp.async.wait_group 0;")

__device__ __forceinline__ void ldsm4(uint32_t* r, uint32_t a) {
    asm volatile("ldmatrix.sync.aligned.m8n8.x4.shared.b16 {%0,%1,%2,%3}, [%4];"
        : "=r"(r[0]), "=r"(r[1]), "=r"(r[2]), "=r"(r[3]) : "r"(a));
}
__device__ __forceinline__ void mma16816(float* c, const uint32_t* a,
                                         uint32_t b0, uint32_t b1) {
    asm volatile("mma.sync.aligned.m16n8k16.row.col.f32.bf16.bf16.f32 "
        "{%0,%1,%2,%3}, {%4,%5,%6,%7}, {%8,%9}, {%0,%1,%2,%3};"
        : "+f"(c[0]), "+f"(c[1]), "+f"(c[2]), "+f"(c[3])
        : "r"(a[0]), "r"(a[1]), "r"(a[2]), "r"(a[3]), "r"(b0), "r"(b1));
}

// ---------------------------------------------------------------------------
// Scratch
// ---------------------------------------------------------------------------
#define AL __align__(256)
__device__ AL __nv_bfloat16 g_xh[M_*D_];
__device__ AL __nv_bfloat16 g_qh[M_*D_];
__device__ AL __nv_bfloat16 g_kh[M_*D_];
__device__ AL __nv_bfloat16 g_vth[M_*D_];
__device__ AL __nv_bfloat16 g_oh[M_*D_],  g_ol[M_*D_];
__device__ AL __nv_bfloat16 g_hh[M_*D_],  g_hl[M_*D_];
__device__ AL __nv_bfloat16 g_sch[(long long)B_*S_*S_];
__device__ AL __nv_bfloat16 g_wh[(long long)B_*S_*S_];
__device__ AL __nv_bfloat16 g_wth[6*D_*D_], g_wtl[3*D_*D_];
__device__ AL float g_att[M_*D_];
__device__ AL float g_onx[M_*D_];
__device__ AL float g_tmp[M_*D_];

// ---------------------------------------------------------------------------
// Tensor-core GEMM: C = alpha * (A @ B^T) (+ bias)
// NPASS=1: plain bf16 (Ah, Bh).  NPASS=3: split hi/lo bf16 (3 MMA passes).
// A [M,K] row-major, B [N,K] row-major. 128x128 block, 8 warps (2x4),
// warp tile 64x32. K-chunk 64, 2-stage cp.async pipeline.
// OUT_MODE 0: fp32; 1: split hi/lo bf16; 2: single bf16.
// BIAS_MODE 0: none; 1: per-col (n); 2: per-row (m).
// ---------------------------------------------------------------------------
#define PITCH 144
#define ARRB  (128*PITCH)       // 18432 bytes per array per stage

template<int NPASS>
__device__ __forceinline__ void load_chunk(uint32_t sbase,
    const __nv_bfloat16* const* src, const long long* ldt, int k0, int tid)
{
    constexpr int NARR = (NPASS == 3) ? 4 : 2;
#pragma unroll
    for (int t = 0; t < NARR; ++t) {
#pragma unroll
        for (int j = 0; j < 4; ++j) {
            int idx = tid + j * 256;         // 0..1023
            int r = idx >> 3, seg = idx & 7;
            const void* g = src[t] + (long long)r * ldt[t] + k0 + seg * 8;
            uint32_t d = sbase + t * ARRB + r * PITCH + seg * 16;
            CP_ASYNC16(d, g);
        }
    }
    CP_COMMIT();
}

template<int NPASS, int OUT_MODE, int BIAS_MODE>
__global__ void __launch_bounds__(256, (NPASS == 1) ? 2 : 1)
gemm_tc(const __nv_bfloat16* __restrict__ Ah, const __nv_bfloat16* __restrict__ Al,
        long long lda, long long sA,
        const __nv_bfloat16* __restrict__ Bh, const __nv_bfloat16* __restrict__ Bl,
        long long ldb, long long sB,
        float* __restrict__ Cf, __nv_bfloat16* __restrict__ Ch,
        __nv_bfloat16* __restrict__ Cl, long long ldc, long long sC,
        const float* __restrict__ bias, float alpha, int K)
{
    constexpr int NARR = (NPASS == 3) ? 4 : 2;
    constexpr int STAGE = NARR * ARRB;
    extern __shared__ __align__(16) char smem[];
    const uint32_t smem_base = smem_to_u32(smem);
    const int tid  = threadIdx.x;
    const int lane = tid & 31;
    const int wid  = tid >> 5;
    const int wm = wid >> 2, wn = wid & 3;
    const long long bz = blockIdx.z;
    const long long m0 = (long long)blockIdx.y * 128;
    const long long n0 = (long long)blockIdx.x * 128;

    const __nv_bfloat16* src[NARR];
    long long ldt[NARR];
    if (NPASS == 3) {
        src[0] = Ah + bz*sA + m0*lda;  src[1] = Al + bz*sA + m0*lda;
        src[2] = Bh + bz*sB + n0*ldb;  src[3] = Bl + bz*sB + n0*ldb;
        ldt[0] = lda; ldt[1] = lda; ldt[2] = ldb; ldt[3] = ldb;
    } else {
        src[0] = Ah + bz*sA + m0*lda;  src[1] = Bh + bz*sB + n0*ldb;
        ldt[0] = lda; ldt[1] = ldb;
    }

    float acc[4][4][4];
#pragma unroll
    for (int i = 0; i < 4; ++i)
#pragma unroll
        for (int j = 0; j < 4; ++j)
#pragma unroll
            for (int r = 0; r < 4; ++r) acc[i][j][r] = 0.f;

    // ldmatrix lane addressing
    const int q = lane >> 3, rim = lane & 7;
    const int aRow = wm * 64 + (q & 1) * 8 + rim;   // + i*16
    const int aKc  = (q >> 1) * 8;
    const int bRow = wn * 32 + (q & 1) * 8 + rim;   // + jp*16
    const int bKc  = (q >> 1) * 8;

    const int nch = K >> 6;
    load_chunk<NPASS>(smem_base, src, ldt, 0, tid);

    for (int c = 0; c < nch; ++c) {
        if (c + 1 < nch) {
            load_chunk<NPASS>(smem_base + ((c + 1) & 1) * STAGE, src, ldt,
                              (c + 1) << 6, tid);
            CP_WAIT1();
        } else {
            CP_WAIT0();
        }
        __syncthreads();

        const uint32_t sb = smem_base + (c & 1) * STAGE;
        const uint32_t aH = sb;
        const uint32_t aL = sb + ARRB;                       // NPASS3 only
        const uint32_t bH = sb + (NPASS == 3 ? 2 : 1) * ARRB;
        const uint32_t bL = sb + 3 * ARRB;                   // NPASS3 only
#pragma unroll
        for (int kk = 0; kk < 4; ++kk) {
            uint32_t ah[4][4], al[4][4];
#pragma unroll
            for (int i = 0; i < 4; ++i) {
                uint32_t off = (uint32_t)(aRow + i * 16) * PITCH
                             + (uint32_t)(kk * 16 + aKc) * 2;
                ldsm4(ah[i], aH + off);
                if (NPASS == 3) ldsm4(al[i], aL + off);
            }
#pragma unroll
            for (int jp = 0; jp < 2; ++jp) {
                uint32_t offB = (uint32_t)(bRow + jp * 16) * PITCH
                              + (uint32_t)(kk * 16 + bKc) * 2;
                uint32_t bh[4];
                ldsm4(bh, bH + offB);
                if (NPASS == 3) {
                    uint32_t bl[4];
                    ldsm4(bl, bL + offB);
#pragma unroll
                    for (int i = 0; i < 4; ++i) {
                        mma16816(acc[i][2*jp],   ah[i], bh[0], bh[2]);
                        mma16816(acc[i][2*jp],   ah[i], bl[0], bl[2]);
                        mma16816(acc[i][2*jp],   al[i], bh[0], bh[2]);
                        mma16816(acc[i][2*jp+1], ah[i], bh[1], bh[3]);
                        mma16816(acc[i][2*jp+1], ah[i], bl[1], bl[3]);
                        mma16816(acc[i][2*jp+1], al[i], bh[1], bh[3]);
                    }
                } else {
#pragma unroll
                    for (int i = 0; i < 4; ++i) {
                        mma16816(acc[i][2*jp],   ah[i], bh[0], bh[2]);
                        mma16816(acc[i][2*jp+1], ah[i], bh[1], bh[3]);
                    }
                }
            }
        }
        __syncthreads();
    }

    // Epilogue
    const int g2 = lane >> 2, t4 = lane & 3;
#pragma unroll
    for (int i = 0; i < 4; ++i) {
#pragma unroll
        for (int half = 0; half < 2; ++half) {
            const long long m = m0 + wm * 64 + i * 16 + g2 + half * 8;
            float brow = 0.f;
            if (BIAS_MODE == 2) brow = bias[m];
#pragma unroll
            for (int j = 0; j < 4; ++j) {
                const long long n = n0 + wn * 32 + j * 8 + t4 * 2;
                float v0 = acc[i][j][half * 2 + 0] * alpha;
                float v1 = acc[i][j][half * 2 + 1] * alpha;
                if (BIAS_MODE == 1) { v0 += bias[n]; v1 += bias[n + 1]; }
                if (BIAS_MODE == 2) { v0 += brow;    v1 += brow; }
                const long long cb = bz * sC + m * ldc + n;
                if (OUT_MODE == 0) {
                    *(float2*)(Cf + cb) = make_float2(v0, v1);
                } else if (OUT_MODE == 2) {
                    __nv_bfloat162 h2;
                    h2.x = __float2bfloat16(v0);
                    h2.y = __float2bfloat16(v1);
                    *(__nv_bfloat162*)(Ch + cb) = h2;
                } else {
                    __nv_bfloat16 h0 = __float2bfloat16(v0);
                    __nv_bfloat16 h1 = __float2bfloat16(v1);
                    __nv_bfloat162 h2, l2;
                    h2.x = h0; h2.y = h1;
                    l2.x = __float2bfloat16(v0 - __bfloat162float(h0));
                    l2.y = __float2bfloat16(v1 - __bfloat162float(h1));
                    *(__nv_bfloat162*)(Ch + cb) = h2;
                    *(__nv_bfloat162*)(Cl + cb) = l2;
                }
            }
        }
    }
}

// ---------------------------------------------------------------------------
// fp32 -> bf16 round (single)
// ---------------------------------------------------------------------------
__global__ void __launch_bounds__(256)
round_kernel(const float* __restrict__ in, __nv_bfloat16* __restrict__ o, int n)
{
    int i = (blockIdx.x * 256 + threadIdx.x) * 2;
    for (; i < n; i += gridDim.x * 512) {
        float2 v = *(const float2*)(in + i);
        __nv_bfloat162 h;
        h.x = __float2bfloat16(v.x);
        h.y = __float2bfloat16(v.y);
        *(__nv_bfloat162*)(o + i) = h;
    }
}

// transpose + round single: T[c,r] = bf16(W[r,c])
__global__ void __launch_bounds__(256)
t1_kernel(const float* __restrict__ W, __nv_bfloat16* __restrict__ Th, int R, int C)
{
    __shared__ float tile[32][33];
    const int c0 = blockIdx.x * 32, r0 = blockIdx.y * 32;
    const int tx = threadIdx.x & 31, ty = threadIdx.x >> 5;
#pragma unroll
    for (int i = 0; i < 32; i += 8)
        tile[ty + i][tx] = W[(long long)(r0 + ty + i) * C + c0 + tx];
    __syncthreads();
#pragma unroll
    for (int i = 0; i < 32; i += 8)
        Th[(long long)(c0 + ty + i) * R + r0 + tx] = __float2bfloat16(tile[tx][ty + i]);
}

// transpose + split hi/lo
__global__ void __launch_bounds__(256)
tsplit_kernel(const float* __restrict__ W, __nv_bfloat16* __restrict__ Th,
              __nv_bfloat16* __restrict__ Tl, int R, int C)
{
    __shared__ float tile[32][33];
    const int c0 = blockIdx.x * 32, r0 = blockIdx.y * 32;
    const int tx = threadIdx.x & 31, ty = threadIdx.x >> 5;
#pragma unroll
    for (int i = 0; i < 32; i += 8)
        tile[ty + i][tx] = W[(long long)(r0 + ty + i) * C + c0 + tx];
    __syncthreads();
#pragma unroll
    for (int i = 0; i < 32; i += 8) {
        float v = tile[tx][ty + i];
        __nv_bfloat16 h = __float2bfloat16(v);
        long long o = (long long)(c0 + ty + i) * R + r0 + tx;
        Th[o] = h;
        Tl[o] = __float2bfloat16(v - __bfloat162float(h));
    }
}

// ---------------------------------------------------------------------------
// Row softmax over 2048 bf16 logits -> bf16 weights
// ---------------------------------------------------------------------------
__global__ void __launch_bounds__(256)
softmax_kernel(const __nv_bfloat16* __restrict__ s, __nv_bfloat16* __restrict__ w)
{
    const long long base = (long long)blockIdx.x * S_ + threadIdx.x * 8;
    const int tid = threadIdx.x;
    __shared__ float red[8];

    __nv_bfloat162 lv[4];
    *(uint4*)lv = *(const uint4*)(s + base);
    float v[8];
#pragma unroll
    for (int i = 0; i < 4; ++i) {
        v[2*i]   = __bfloat162float(lv[i].x);
        v[2*i+1] = __bfloat162float(lv[i].y);
    }

    float mx = v[0];
#pragma unroll
    for (int i = 1; i < 8; ++i) mx = fmaxf(mx, v[i]);
#pragma unroll
    for (int o = 16; o; o >>= 1) mx = fmaxf(mx, __shfl_xor_sync(0xffffffffu, mx, o));
    if ((tid & 31) == 0) red[tid >> 5] = mx;
    __syncthreads();
    mx = red[0];
#pragma unroll
    for (int i = 1; i < 8; ++i) mx = fmaxf(mx, red[i]);
    __syncthreads();

    float sum = 0.f;
#pragma unroll
    for (int i = 0; i < 8; ++i) { v[i] = __expf(v[i] - mx); sum += v[i]; }
#pragma unroll
    for (int o = 16; o; o >>= 1) sum += __shfl_xor_sync(0xffffffffu, sum, o);
    if ((tid & 31) == 0) red[tid >> 5] = sum;
    __syncthreads();
    float tot = 0.f;
#pragma unroll
    for (int i = 0; i < 8; ++i) tot += red[i];

    const float inv = 1.0f / tot;
    __nv_bfloat162 ov[4];
#pragma unroll
    for (int i = 0; i < 4; ++i) {
        ov[i].x = __float2bfloat16(v[2*i]   * inv);
        ov[i].y = __float2bfloat16(v[2*i+1] * inv);
    }
    *(uint4*)(w + base) = *(uint4*)ov;
}

// ---------------------------------------------------------------------------
// out = LN(x + att) -> fp32 + split bf16
// ---------------------------------------------------------------------------
__global__ void __launch_bounds__(256)
add_ln_kernel(const float* __restrict__ x, const float* __restrict__ a,
              const float* __restrict__ gam, const float* __restrict__ bet,
              float* __restrict__ out, __nv_bfloat16* __restrict__ oh,
              __nv_bfloat16* __restrict__ ol)
{
    const long long base = (long long)blockIdx.x * D_;
    const int tid = threadIdx.x;
    __shared__ float r1[8], r2[8];
    const int i0 = tid * 2;

    float2 xa = *(const float2*)(x + base + i0);
    float2 aa = *(const float2*)(a + base + i0);
    float u0 = xa.x + aa.x, u1 = xa.y + aa.y;

    float s = u0 + u1, sq = u0*u0 + u1*u1;
#pragma unroll
    for (int o = 16; o; o >>= 1) {
        s  += __shfl_xor_sync(0xffffffffu, s,  o);
        sq += __shfl_xor_sync(0xffffffffu, sq, o);
    }
    if ((tid & 31) == 0) { r1[tid >> 5] = s; r2[tid >> 5] = sq; }
    __syncthreads();
    float ts = 0.f, tq = 0.f;
#pragma unroll
    for (int i = 0; i < 8; ++i) { ts += r1[i]; tq += r2[i]; }
    const float mean = ts * (1.0f/512.0f);
    const float var  = tq * (1.0f/512.0f) - mean*mean;
    const float rstd = rsqrtf(var + 1e-5f);

    float o0 = (u0 - mean)*rstd*gam[i0]   + bet[i0];
    float o1 = (u1 - mean)*rstd*gam[i0+1] + bet[i0+1];
    *(float2*)(out + base + i0) = make_float2(o0, o1);
    __nv_bfloat16 h0 = __float2bfloat16(o0), h1 = __float2bfloat16(o1);
    __nv_bfloat162 h2, l2;
    h2.x = h0; h2.y = h1;
    l2.x = __float2bfloat16(o0 - __bfloat162float(h0));
    l2.y = __float2bfloat16(o1 - __bfloat162float(h1));
    *(__nv_bfloat162*)(oh + base + i0) = h2;
    *(__nv_bfloat162*)(ol + base + i0) = l2;
}

// out = LN(gelu(res + t)) -> split bf16
__global__ void __launch_bounds__(256)
res_gelu_ln_kernel(const float* __restrict__ t, const float* __restrict__ res,
                   const float* __restrict__ gam, const float* __restrict__ bet,
                   __nv_bfloat16* __restrict__ oh, __nv_bfloat16* __restrict__ ol)
{
    const long long base = (long long)blockIdx.x * D_;
    const int tid = threadIdx.x;
    __shared__ float r1[8], r2[8];
    const int i0 = tid * 2;

    float2 ta = *(const float2*)(t + base + i0);
    float2 ra = *(const float2*)(res + base + i0);
    float u0 = ra.x + ta.x, u1 = ra.y + ta.y;
    float g0 = 0.5f * u0 * (1.0f + erff(u0 * 0.70710678118654752f));
    float g1 = 0.5f * u1 * (1.0f + erff(u1 * 0.70710678118654752f));

    float s = g0 + g1, sq = g0*g0 + g1*g1;
#pragma unroll
    for (int o = 16; o; o >>= 1) {
        s  += __shfl_xor_sync(0xffffffffu, s,  o);
        sq += __shfl_xor_sync(0xffffffffu, sq, o);
    }
    if ((tid & 31) == 0) { r1[tid >> 5] = s; r2[tid >> 5] = sq; }
    __syncthreads();
    float ts = 0.f, tq = 0.f;
#pragma unroll
    for (int i = 0; i < 8; ++i) { ts += r1[i]; tq += r2[i]; }
    const float mean = ts * (1.0f/512.0f);
    const float var  = tq * (1.0f/512.0f) - mean*mean;
    const float rstd = rsqrtf(var + 1e-5f);

    float o0 = (g0 - mean)*rstd*gam[i0]   + bet[i0];
    float o1 = (g1 - mean)*rstd*gam[i0+1] + bet[i0+1];
    __nv_bfloat16 h0 = __float2bfloat16(o0), h1 = __float2bfloat16(o1);
    __nv_bfloat162 h2, l2;
    h2.x = h0; h2.y = h1;
    l2.x = __float2bfloat16(o0 - __bfloat162float(h0));
    l2.y = __float2bfloat16(o1 - __bfloat162float(h1));
    *(__nv_bfloat162*)(oh + base + i0) = h2;
    *(__nv_bfloat162*)(ol + base + i0) = l2;
}

// ---------------------------------------------------------------------------
// Launch sequence
// ---------------------------------------------------------------------------
#define SMEM_NP1 (2*2*ARRB)     // 73728
#define SMEM_NP3 (2*4*ARRB)     // 147456

extern "C" void kernel_launch(void* const* d_in, const int* in_sizes, int n_in,
                              void* d_out, int out_size)
{
    const float* x    = (const float*)d_in[0];
    const float* Wq   = (const float*)d_in[1];
    const float* bq   = (const float*)d_in[2];
    const float* Wk   = (const float*)d_in[3];
    const float* bk   = (const float*)d_in[4];
    const float* Wv   = (const float*)d_in[5];
    const float* bv   = (const float*)d_in[6];
    const float* ln0g = (const float*)d_in[7];
    const float* ln0b = (const float*)d_in[8];
    const float* W1   = (const float*)d_in[9];
    const float* b1   = (const float*)d_in[10];
    const float* ln1g = (const float*)d_in[11];
    const float* ln1b = (const float*)d_in[12];
    const float* W2   = (const float*)d_in[13];
    const float* b2   = (const float*)d_in[14];
    const float* ln2g = (const float*)d_in[15];
    const float* ln2b = (const float*)d_in[16];
    const float* W3   = (const float*)d_in[17];
    const float* b3   = (const float*)d_in[18];

    __nv_bfloat16 *xh, *qh, *kh, *vth, *oh, *ol, *hh, *hl, *sch, *wh, *wth, *wtl;
    float *att, *onx, *tmp;
    cudaGetSymbolAddress((void**)&xh,  g_xh);
    cudaGetSymbolAddress((void**)&qh,  g_qh);
    cudaGetSymbolAddress((void**)&kh,  g_kh);
    cudaGetSymbolAddress((void**)&vth, g_vth);
    cudaGetSymbolAddress((void**)&oh,  g_oh);  cudaGetSymbolAddress((void**)&ol, g_ol);
    cudaGetSymbolAddress((void**)&hh,  g_hh);  cudaGetSymbolAddress((void**)&hl, g_hl);
    cudaGetSymbolAddress((void**)&sch, g_sch); cudaGetSymbolAddress((void**)&wh, g_wh);
    cudaGetSymbolAddress((void**)&wth, g_wth); cudaGetSymbolAddress((void**)&wtl, g_wtl);
    cudaGetSymbolAddress((void**)&att, g_att);
    cudaGetSymbolAddress((void**)&onx, g_onx); cudaGetSymbolAddress((void**)&tmp, g_tmp);

    cudaFuncSetAttribute(gemm_tc<1,2,1>, cudaFuncAttributeMaxDynamicSharedMemorySize, SMEM_NP1);
    cudaFuncSetAttribute(gemm_tc<1,2,2>, cudaFuncAttributeMaxDynamicSharedMemorySize, SMEM_NP1);
    cudaFuncSetAttribute(gemm_tc<1,2,0>, cudaFuncAttributeMaxDynamicSharedMemorySize, SMEM_NP1);
    cudaFuncSetAttribute(gemm_tc<1,0,0>, cudaFuncAttributeMaxDynamicSharedMemorySize, SMEM_NP1);
    cudaFuncSetAttribute(gemm_tc<3,0,1>, cudaFuncAttributeMaxDynamicSharedMemorySize, SMEM_NP3);

    const dim3 t256(256);
    const long long DD = (long long)D_ * D_;
    const long long sSD = (long long)S_ * D_;
    const long long sSS = (long long)S_ * S_;

    // Weight prep: Wq/Wk/Wv single bf16 transposed; W1/W2/W3 split transposed
    t1_kernel<<<dim3(16,16), t256>>>(Wq, wth + 0*DD, D_, D_);
    t1_kernel<<<dim3(16,16), t256>>>(Wk, wth + 1*DD, D_, D_);
    t1_kernel<<<dim3(16,16), t256>>>(Wv, wth + 2*DD, D_, D_);
    tsplit_kernel<<<dim3(16,16), t256>>>(W1, wth + 3*DD, wtl + 0*DD, D_, D_);
    tsplit_kernel<<<dim3(16,16), t256>>>(W2, wth + 4*DD, wtl + 1*DD, D_, D_);
    tsplit_kernel<<<dim3(16,16), t256>>>(W3, wth + 5*DD, wtl + 2*DD, D_, D_);

    round_kernel<<<4096, t256>>>(x, xh, M_*D_);

    // q/k = x @ W + b  (bf16 out)
    gemm_tc<1,2,1><<<dim3(4,128,1), t256, SMEM_NP1>>>(xh, nullptr, D_, 0,
        wth + 0*DD, nullptr, D_, 0, nullptr, qh, nullptr, D_, 0, bq, 1.f, D_);
    gemm_tc<1,2,1><<<dim3(4,128,1), t256, SMEM_NP1>>>(xh, nullptr, D_, 0,
        wth + 1*DD, nullptr, D_, 0, nullptr, kh, nullptr, D_, 0, bk, 1.f, D_);

    // vT[feat, token] = Wv^T @ x^T + bv (row bias), ldc = 16384
    gemm_tc<1,2,2><<<dim3(128,4,1), t256, SMEM_NP1>>>(wth + 2*DD, nullptr, D_, 0,
        xh, nullptr, D_, 0, nullptr, vth, nullptr, (long long)M_, 0, bv, 1.f, D_);

    // scores[b] = SCALE * q_b @ k_b^T  (bf16 out)
    gemm_tc<1,2,0><<<dim3(16,16,B_), t256, SMEM_NP1>>>(qh, nullptr, D_, sSD,
        kh, nullptr, D_, sSD, nullptr, sch, nullptr, S_, sSS, nullptr, SCALE, D_);

    softmax_kernel<<<M_, t256>>>(sch, wh);

    // att[b] = w_b @ v_b   (fp32 out)
    gemm_tc<1,0,0><<<dim3(4,16,B_), t256, SMEM_NP1>>>(wh, nullptr, S_, sSS,
        vth, nullptr, (long long)M_, (long long)S_, att, nullptr, nullptr, D_, sSD,
        nullptr, 1.f, S_);

    add_ln_kernel<<<M_, t256>>>(x, att, ln0g, ln0b, onx, oh, ol);

    gemm_tc<3,0,1><<<dim3(4,128,1), t256, SMEM_NP3>>>(oh, ol, D_, 0,
        wth + 3*DD, wtl + 0*DD, D_, 0, tmp, nullptr, nullptr, D_, 0, b1, 1.f, D_);
    res_gelu_ln_kernel<<<M_, t256>>>(tmp, onx, ln1g, ln1b, hh, hl);

    gemm_tc<3,0,1><<<dim3(4,128,1), t256, SMEM_NP3>>>(hh, hl, D_, 0,
        wth + 4*DD, wtl + 1*DD, D_, 0, tmp, nullptr, nullptr, D_, 0, b2, 1.f, D_);
    res_gelu_ln_kernel<<<M_, t256>>>(tmp, onx, ln2g, ln2b, hh, hl);

    gemm_tc<3,0,1><<<dim3(4,128,1), t256, SMEM_NP3>>>(hh, hl, D_, 0,
        wth + 5*DD, wtl + 2*DD, D_, 0, (float*)d_out, nullptr, nullptr, D_, 0,
        b3, 1.f, D_);
}